// round 6
// baseline (speedup 1.0000x reference)
#include <cuda_runtime.h>
#include <math.h>
#include <stdint.h>

#define NN 1024
#define DD 64
#define TI 4
#define GRID (NN / TI)        // 256 CTAs; 2/SM x 148 SMs = 296 slots >= 256

// Globals exchanged across CTAs (no allocation allowed in kernel_launch).
__device__ float g_s1[NN];
__device__ float g_ssrc[NN * DD];
// Device-wide barrier state: A self-resets each use; R is monotonic across
// launches and compared by != (replay-safe, no per-launch init needed).
__device__ unsigned g_barA = 0;
__device__ unsigned g_barR = 0;

// ---- packed fp32x2 helpers (sm_100a: ADD2 / FFMA2) -------------------------
__device__ __forceinline__ float2 f2_add(float2 a, float2 b) {
    float2 c;
    asm("add.rn.f32x2 %0, %1, %2;"
        : "=l"(*reinterpret_cast<unsigned long long*>(&c))
        : "l"(*reinterpret_cast<const unsigned long long*>(&a)),
          "l"(*reinterpret_cast<const unsigned long long*>(&b)));
    return c;
}
__device__ __forceinline__ float2 f2_fma(float2 a, float2 b, float2 c) {
    float2 d;
    asm("fma.rn.f32x2 %0, %1, %2, %3;"
        : "=l"(*reinterpret_cast<unsigned long long*>(&d))
        : "l"(*reinterpret_cast<const unsigned long long*>(&a)),
          "l"(*reinterpret_cast<const unsigned long long*>(&b)),
          "l"(*reinterpret_cast<const unsigned long long*>(&c)));
    return d;
}

// ---------------------------------------------------------------------------
// Fused kernel: projections -> grid barrier -> softmax -> contraction.
// 256 blocks x 512 threads, 2 CTAs/SM (all CTAs co-resident -> barrier safe).
// smem union: fw_sh (pre-phase, 33.3 KB) overlays att2+s1 (post-barrier).
// ---------------------------------------------------------------------------
__global__ __launch_bounds__(512, 2) void gat_fused_kernel(
    const float* __restrict__ x,
    const int*   __restrict__ adj,
    const float* __restrict__ f_w,   // [DD][2*DD] row-major
    const float* __restrict__ f_b,   // [DD]
    const float* __restrict__ w_w,   // [1][2*DD]
    float* __restrict__ out)
{
    __shared__ __align__(16) char smU[NN * TI * 8 + NN * 4];  // 36864 B union
    __shared__ float t_sh[TI * DD];     // own rows' t — never leaves the CTA
    __shared__ float xs[TI][DD];
    __shared__ float w1_sh[DD];
    __shared__ float sred[TI][2];
    __shared__ float wsum[16 * TI];
    __shared__ float rowinv[TI];

    float*  fw_sh = reinterpret_cast<float*>(smU);               // [128][65]
    float2* att2  = reinterpret_cast<float2*>(smU);              // [NN*TI]
    float*  s1_sh = reinterpret_cast<float*>(smU + NN * TI * 8); // [NN]

    const int tid  = threadIdx.x;
    const int row0 = blockIdx.x * TI;
    const int wid  = tid >> 5;
    const int lane = tid & 31;

    // ===== Phase 0: projections for this CTA's 4 nodes =====================
    for (int i = tid; i < DD * 128; i += 512)
        fw_sh[(i & 127) * 65 + (i >> 7)] = f_w[i];   // stride-65: conflict-free
    if (tid < DD) w1_sh[tid] = w_w[tid];
    if (tid < TI * DD) xs[tid >> 6][tid & 63] = x[row0 * DD + tid];
    __syncthreads();

    {   // thread -> (m, ln, d): dot(x[ln], F_m[d]) over k=0..63
        const int m  = tid >> 8;        // 0: F1 -> g_ssrc, 1: F2 -> t_sh
        const int ln = (tid >> 6) & 3;
        const int d  = tid & 63;
        float a = 0.f;
#pragma unroll
        for (int k = 0; k < DD; ++k)
            a = fmaf(xs[ln][k], fw_sh[(m * 64 + k) * 65 + d], a);
        if (m == 0) g_ssrc[(row0 + ln) * DD + d] = a;
        else        t_sh[ln * DD + d] = a + f_b[d];

        // s1[node] = x[node] . w1  (first 256 threads, 2 warps per node)
        if (tid < 256) {
            float p = xs[ln][d] * w1_sh[d];
#pragma unroll
            for (int off = 16; off > 0; off >>= 1)
                p += __shfl_down_sync(0xffffffffu, p, off);
            if ((tid & 31) == 0) sred[ln][(tid >> 5) & 1] = p;
        }
    }
    __syncthreads();
    if (tid < TI) g_s1[row0 + tid] = sred[tid][0] + sred[tid][1];

    // ===== Grid-wide barrier (all 256 CTAs co-resident) =====================
    __threadfence();          // publish g_ssrc / g_s1
    __syncthreads();
    if (tid == 0) {
        unsigned r0 = *(volatile unsigned*)&g_barR;
        unsigned old = atomicAdd(&g_barA, 1u);
        if (old == GRID - 1) {
            *(volatile unsigned*)&g_barA = 0u;     // reset for next launch
            atomicAdd(&g_barR, 1u);                // release
        } else {
            while (*(volatile unsigned*)&g_barR == r0) { }
        }
    }
    __syncthreads();
    __threadfence();          // acquire: see other CTAs' g_ssrc / g_s1

    // ===== Phase 1: softmax numerators ======================================
    for (int i = tid; i < NN; i += 512) s1_sh[i] = g_s1[i];
    __syncthreads();
    {
        float ls[TI] = {0.f, 0.f, 0.f, 0.f};
#pragma unroll
        for (int k = 0; k < 2; ++k) {
            int j = wid * 64 + k * 32 + lane;
            float ev = __expf(s1_sh[j]);
#pragma unroll
            for (int rr = 0; rr < TI; ++rr) {
                int a = adj[(row0 + rr) * NN + j];          // coalesced
                float e = (a > 0) ? ev : 0.f;
                att2[j * TI + rr] = make_float2(e, e);
                ls[rr] += e;
            }
        }
#pragma unroll
        for (int rr = 0; rr < TI; ++rr) {
            float v = ls[rr];
#pragma unroll
            for (int off = 16; off > 0; off >>= 1)
                v += __shfl_xor_sync(0xffffffffu, v, off);
            if (lane == 0) wsum[wid * TI + rr] = v;
        }
    }
    __syncthreads();
    if (tid < TI) {
        float s = 0.f;
#pragma unroll
        for (int g = 0; g < 16; ++g) s += wsum[g * TI + tid];
        rowinv[tid] = 1.f / s;
    }

    // ===== Phase 2: contraction (proven R3 inner loop) ======================
    const int h  = lane >> 4;        // 0: rows {0,1}, 1: rows {2,3}
    const int q  = lane & 15;        // d quad: d = 4q..4q+3
    const int jg = wid;              // j group: [jg*64, (jg+1)*64)

    float2 t2[2][2];
#pragma unroll
    for (int rr = 0; rr < 2; ++rr)
#pragma unroll
        for (int p = 0; p < 2; ++p)
            t2[rr][p] = *reinterpret_cast<const float2*>(
                &t_sh[(2 * h + rr) * DD + 4 * q + 2 * p]);

    float2 acc[2][2];
    acc[0][0] = acc[0][1] = acc[1][0] = acc[1][1] = make_float2(0.f, 0.f);

    const float4* __restrict__ sp4 =
        reinterpret_cast<const float4*>(g_ssrc + jg * 64 * DD) + q;
    const float4* __restrict__ ap4 =
        reinterpret_cast<const float4*>(att2 + jg * 64 * TI) + h;

#pragma unroll 16
    for (int k = 0; k < 64; ++k) {
        float4 s4 = sp4[k * (DD / 4)];   // one coalesced 256B/warp LDG.128
        float4 e4 = ap4[k * 2];          // {e2h,e2h,e2h+1,e2h+1}
        float2 sa = make_float2(s4.x, s4.y);
        float2 sb = make_float2(s4.z, s4.w);

#define GAT_STEP(RR, EPAIR)                                  \
        {                                                    \
            float2 ua = f2_add(sa, t2[RR][0]);               \
            float2 ub = f2_add(sb, t2[RR][1]);               \
            ua.x = fmaxf(ua.x, 0.f);  ua.y = fmaxf(ua.y, 0.f); \
            ub.x = fmaxf(ub.x, 0.f);  ub.y = fmaxf(ub.y, 0.f); \
            acc[RR][0] = f2_fma((EPAIR), ua, acc[RR][0]);    \
            acc[RR][1] = f2_fma((EPAIR), ub, acc[RR][1]);    \
        }
        GAT_STEP(0, make_float2(e4.x, e4.y))
        GAT_STEP(1, make_float2(e4.z, e4.w))
#undef GAT_STEP
    }

    // ===== Epilogue: reduce 16 warp-partials, normalize, store ==============
    __syncthreads();                       // everyone done reading att2
    float* part = reinterpret_cast<float*>(att2);   // reuse: [16][TI][DD]
#pragma unroll
    for (int rr = 0; rr < 2; ++rr) {
        float4 v = make_float4(acc[rr][0].x, acc[rr][0].y,
                               acc[rr][1].x, acc[rr][1].y);
        *reinterpret_cast<float4*>(
            &part[(jg * TI + 2 * h + rr) * DD + 4 * q]) = v;
    }
    __syncthreads();

    if (tid < TI * DD) {                   // 256 threads: (rr, d)
        int rr = tid >> 6;
        int d  = tid & 63;
        float s = 0.f;
#pragma unroll
        for (int g = 0; g < 16; ++g)
            s += part[(g * TI + rr) * DD + d];
        out[(row0 + rr) * DD + d] = s * rowinv[rr];
    }
}

// ---------------------------------------------------------------------------
// Inputs (metadata order): 0 x[1024,64] f32, 1 adj[1024,1024] i32,
// 2 src i64 (unused), 3 tgt i64 (unused), 4 Msrc (unused), 5 Mtgt (unused),
// 6 f_w[64,128] f32, 7 f_b[64] f32, 8 w_w[1,128] f32, 9 w_b[1] f32 (cancels).
// Output: o[1024,64] f32.
// ---------------------------------------------------------------------------
extern "C" void kernel_launch(void* const* d_in, const int* in_sizes, int n_in,
                              void* d_out, int out_size)
{
    const float* x   = (const float*)d_in[0];
    const int*   adj = (const int*)d_in[1];
    const float* f_w = (const float*)d_in[6];
    const float* f_b = (const float*)d_in[7];
    const float* w_w = (const float*)d_in[8];
    float* out = (float*)d_out;

    gat_fused_kernel<<<GRID, 512>>>(x, adj, f_w, f_b, w_w, out);
}

// round 7
// speedup vs baseline: 1.0241x; 1.0241x over previous
#include <cuda_runtime.h>
#include <math.h>
#include <stdint.h>

#define NN 1024
#define DD 64
#define TI 4

// Scratch (device globals — no allocation allowed in kernel_launch).
__device__ float g_s1[NN];
__device__ float g_ssrc[NN * DD];
__device__ float g_t[NN * DD];

// ---- packed fp32x2 helpers (sm_100a: ADD2 / FFMA2) -------------------------
__device__ __forceinline__ float2 f2_add(float2 a, float2 b) {
    float2 c;
    asm("add.rn.f32x2 %0, %1, %2;"
        : "=l"(*reinterpret_cast<unsigned long long*>(&c))
        : "l"(*reinterpret_cast<const unsigned long long*>(&a)),
          "l"(*reinterpret_cast<const unsigned long long*>(&b)));
    return c;
}
__device__ __forceinline__ float2 f2_fma(float2 a, float2 b, float2 c) {
    float2 d;
    asm("fma.rn.f32x2 %0, %1, %2, %3;"
        : "=l"(*reinterpret_cast<unsigned long long*>(&d))
        : "l"(*reinterpret_cast<const unsigned long long*>(&a)),
          "l"(*reinterpret_cast<const unsigned long long*>(&b)),
          "l"(*reinterpret_cast<const unsigned long long*>(&c)));
    return d;
}

__device__ __forceinline__ void cp16(uint32_t saddr, const void* g) {
    asm volatile("cp.async.cg.shared.global [%0], [%1], 16;"
                 :: "r"(saddr), "l"(g) : "memory");
}

// ---------------------------------------------------------------------------
// Kernel A: per-node projections. 128 blocks x 512 threads, 8 nodes/block.
// (unchanged from R5 — proven)
// ---------------------------------------------------------------------------
__global__ __launch_bounds__(512, 1) void gat_pre_kernel(
    const float* __restrict__ x,
    const float* __restrict__ f_w,   // [DD][2*DD] row-major
    const float* __restrict__ f_b,   // [DD]
    const float* __restrict__ w_w)   // [1][2*DD]
{
    __shared__ float fw_sh[128][65];
    __shared__ float xs[8][DD];
    __shared__ float w1_sh[DD];
    __shared__ float sred[8][2];

    const int tid   = threadIdx.x;
    const int node0 = blockIdx.x * 8;

    for (int i = tid; i < DD * 128; i += 512)
        fw_sh[i & 127][i >> 7] = f_w[i];          // stride-65: no conflicts
    if (tid < DD) w1_sh[tid] = w_w[tid];
    xs[tid >> 6][tid & 63] = x[node0 * DD + tid];
    __syncthreads();

    const int ln   = tid >> 6;
    const int d    = tid & 63;
    const int node = node0 + ln;

    float a1 = 0.f, a2 = 0.f;
#pragma unroll
    for (int k = 0; k < DD; ++k) {
        float xa = xs[ln][k];
        a1 = fmaf(xa, fw_sh[k][d], a1);
        a2 = fmaf(xa, fw_sh[DD + k][d], a2);
    }
    g_ssrc[node * DD + d] = a1;
    g_t[node * DD + d]    = a2 + f_b[d];

    float p = xs[ln][d] * w1_sh[d];
#pragma unroll
    for (int off = 16; off > 0; off >>= 1)
        p += __shfl_down_sync(0xffffffffu, p, off);
    if ((tid & 31) == 0) sred[ln][(tid >> 5) & 1] = p;
    __syncthreads();
    if (d == 0) g_s1[node] = sred[ln][0] + sred[ln][1];
}

// ---------------------------------------------------------------------------
// Kernel B: masked softmax + weighted-relu contraction.
// 256 blocks (TI=4 rows) x 512 threads, 2 CTAs/SM, ~69 KB dynamic smem.
// PER-WARP cp.async pipeline: warp w stages its 64 j-rows through a private
// 8-row smem ring (group = 2 rows = 512 B), depth 3. No __syncthreads and no
// extra registers in the main loop — only wait_group + __syncwarp.
// ---------------------------------------------------------------------------
#define SM_ATT   0                        // float2 att2[NN*TI]   32768 B
#define SM_STAGE 32768                    // float stage[16][8][64] 32768 B
#define SM_S1    65536                    // float s1_sh[NN]       4096 B
#define SM_T     69632                    // float t_sh[TI*DD]     1024 B
#define SM_WSUM  70656                    // float wsum[16*TI]      256 B
#define SM_RINV  70912                    // float rowinv[TI]
#define SM_SIZE  70976

__global__ __launch_bounds__(512, 2) void gat_main_kernel(
    const int* __restrict__ adj,
    float* __restrict__ out)
{
    extern __shared__ char dsm[];
    float2* att2   = reinterpret_cast<float2*>(dsm + SM_ATT);
    float*  stage  = reinterpret_cast<float*>(dsm + SM_STAGE);
    float*  s1_sh  = reinterpret_cast<float*>(dsm + SM_S1);
    float*  t_sh   = reinterpret_cast<float*>(dsm + SM_T);
    float*  wsum   = reinterpret_cast<float*>(dsm + SM_WSUM);
    float*  rowinv = reinterpret_cast<float*>(dsm + SM_RINV);

    const int tid  = threadIdx.x;
    const int row0 = blockIdx.x * TI;
    const int wid  = tid >> 5;
    const int lane = tid & 31;

    // Per-warp stage ring: 8 rows x 256 B. Lane copies chunk (lane&15) of
    // row pair-member (lane>>4): one cp.async per lane moves 2 rows / warp.
    const uint32_t st_warp =
        (uint32_t)__cvta_generic_to_shared(stage) + (uint32_t)wid * 2048u;
    const uint32_t st_lane = ((uint32_t)(lane >> 4)) * 256u +
                             ((uint32_t)(lane & 15)) * 16u;
    const char* gsrc = reinterpret_cast<const char*>(g_ssrc) +
                       ((wid * 64 + (lane >> 4)) * 256 + (lane & 15) * 16);

#define ISSUE_GROUP(GP)                                                    \
    {                                                                      \
        cp16(st_warp + (uint32_t)(((2 * (GP)) & 7) * 256) + st_lane,       \
             gsrc + (size_t)(2 * (GP)) * 256);                             \
        asm volatile("cp.async.commit_group;" ::: "memory");               \
    }

    // Prologue: 3 groups in flight (rows 0..5) — overlap with softmax phase.
    ISSUE_GROUP(0) ISSUE_GROUP(1) ISSUE_GROUP(2)

    for (int i = tid; i < NN; i += 512) s1_sh[i] = g_s1[i];
    if (tid < TI * DD) t_sh[tid] = g_t[row0 * DD + tid];
    __syncthreads();

    // --- softmax numerators: e[j][r] = adj[r][j]>0 ? exp(s1[j]) : 0 ---------
    {
        float ls[TI] = {0.f, 0.f, 0.f, 0.f};
#pragma unroll
        for (int k = 0; k < 2; ++k) {
            int j = wid * 64 + k * 32 + lane;
            float ev = __expf(s1_sh[j]);
#pragma unroll
            for (int rr = 0; rr < TI; ++rr) {
                int a = adj[(row0 + rr) * NN + j];          // coalesced
                float e = (a > 0) ? ev : 0.f;
                att2[j * TI + rr] = make_float2(e, e);
                ls[rr] += e;
            }
        }
#pragma unroll
        for (int rr = 0; rr < TI; ++rr) {
            float v = ls[rr];
#pragma unroll
            for (int off = 16; off > 0; off >>= 1)
                v += __shfl_xor_sync(0xffffffffu, v, off);
            if (lane == 0) wsum[wid * TI + rr] = v;
        }
    }
    __syncthreads();
    if (tid < TI) {
        float s = 0.f;
#pragma unroll
        for (int g = 0; g < 16; ++g) s += wsum[g * TI + tid];
        rowinv[tid] = 1.f / s;
    }

    // --- contraction: acc[r] += e[j][r] * relu(s_src[j] + t[r]) -------------
    const int h = lane >> 4;         // 0: rows {0,1}, 1: rows {2,3}
    const int q = lane & 15;         // d quad: d = 4q..4q+3

    float2 t2[2][2];
#pragma unroll
    for (int rr = 0; rr < 2; ++rr)
#pragma unroll
        for (int p = 0; p < 2; ++p)
            t2[rr][p] = *reinterpret_cast<const float2*>(
                &t_sh[(2 * h + rr) * DD + 4 * q + 2 * p]);

    float2 acc[2][2];
    acc[0][0] = acc[0][1] = acc[1][0] = acc[1][1] = make_float2(0.f, 0.f);

    const float*  swarp = stage + wid * 512;   // this warp's 8-row ring
    const float4* ap4   = reinterpret_cast<const float4*>(att2 + wid * 64 * TI) + h;

#define CONSUME_ROW(JJ)                                                     \
    {                                                                       \
        float4 s4 = *reinterpret_cast<const float4*>(                       \
            swarp + ((JJ) & 7) * 64 + 4 * q);                               \
        float4 e4 = ap4[(JJ) * 2];                                          \
        float2 sa = make_float2(s4.x, s4.y);                                \
        float2 sb = make_float2(s4.z, s4.w);                                \
        float2 ua, ub;                                                      \
        ua = f2_add(sa, t2[0][0]);  ub = f2_add(sb, t2[0][1]);              \
        ua.x = fmaxf(ua.x, 0.f); ua.y = fmaxf(ua.y, 0.f);                   \
        ub.x = fmaxf(ub.x, 0.f); ub.y = fmaxf(ub.y, 0.f);                   \
        acc[0][0] = f2_fma(make_float2(e4.x, e4.y), ua, acc[0][0]);         \
        acc[0][1] = f2_fma(make_float2(e4.x, e4.y), ub, acc[0][1]);         \
        ua = f2_add(sa, t2[1][0]);  ub = f2_add(sb, t2[1][1]);              \
        ua.x = fmaxf(ua.x, 0.f); ua.y = fmaxf(ua.y, 0.f);                   \
        ub.x = fmaxf(ub.x, 0.f); ub.y = fmaxf(ub.y, 0.f);                   \
        acc[1][0] = f2_fma(make_float2(e4.z, e4.w), ua, acc[1][0]);         \
        acc[1][1] = f2_fma(make_float2(e4.z, e4.w), ub, acc[1][1]);         \
    }

    // Steady state: wait group gp (keep ≤2 pending), consume 2 rows, refill.
#pragma unroll 4
    for (int gp = 0; gp < 29; ++gp) {
        asm volatile("cp.async.wait_group 2;" ::: "memory");
        __syncwarp();
        CONSUME_ROW(2 * gp)
        CONSUME_ROW(2 * gp + 1)
        ISSUE_GROUP(gp + 3)
    }
    // Tail: groups 29..31 already issued; drain all, consume rows 58..63.
    asm volatile("cp.async.wait_group 0;" ::: "memory");
    __syncwarp();
#pragma unroll
    for (int jj = 58; jj < 64; ++jj) CONSUME_ROW(jj)
#undef CONSUME_ROW
#undef ISSUE_GROUP

    // --- epilogue: reduce 16 warp-partials, normalize, store ----------------
    __syncthreads();                       // everyone done reading att2
    float* part = reinterpret_cast<float*>(att2);   // reuse: [16][TI][DD]
#pragma unroll
    for (int rr = 0; rr < 2; ++rr) {
        float4 v = make_float4(acc[rr][0].x, acc[rr][0].y,
                               acc[rr][1].x, acc[rr][1].y);
        *reinterpret_cast<float4*>(
            &part[(wid * TI + 2 * h + rr) * DD + 4 * q]) = v;
    }
    __syncthreads();

    if (tid < TI * DD) {                   // 256 threads: (rr, d)
        int rr = tid >> 6;
        int d  = tid & 63;
        float s = 0.f;
#pragma unroll
        for (int g = 0; g < 16; ++g)
            s += part[(g * TI + rr) * DD + d];
        out[(row0 + rr) * DD + d] = s * rowinv[rr];
    }
}

// ---------------------------------------------------------------------------
// Inputs (metadata order): 0 x[1024,64] f32, 1 adj[1024,1024] i32,
// 2 src i64 (unused), 3 tgt i64 (unused), 4 Msrc (unused), 5 Mtgt (unused),
// 6 f_w[64,128] f32, 7 f_b[64] f32, 8 w_w[1,128] f32, 9 w_b[1] f32 (cancels).
// Output: o[1024,64] f32.
// ---------------------------------------------------------------------------
extern "C" void kernel_launch(void* const* d_in, const int* in_sizes, int n_in,
                              void* d_out, int out_size)
{
    const float* x   = (const float*)d_in[0];
    const int*   adj = (const int*)d_in[1];
    const float* f_w = (const float*)d_in[6];
    const float* f_b = (const float*)d_in[7];
    const float* w_w = (const float*)d_in[8];
    float* out = (float*)d_out;

    cudaFuncSetAttribute(gat_main_kernel,
                         cudaFuncAttributeMaxDynamicSharedMemorySize,
                         SM_SIZE);

    gat_pre_kernel<<<128, 512>>>(x, f_w, f_b, w_w);
    gat_main_kernel<<<NN / TI, 512, SM_SIZE>>>(adj, out);
}

// round 8
// speedup vs baseline: 1.1279x; 1.1014x over previous
#include <cuda_runtime.h>
#include <math.h>
#include <stdint.h>

#define NN 1024
#define DD 64
#define TI 4

// Scratch (device globals — no allocation allowed in kernel_launch).
__device__ float g_s1[NN];
__device__ float g_ssrc[NN * DD];
__device__ float g_t[NN * DD];

// ---- packed fp32x2 helpers (sm_100a: ADD2 / FFMA2) -------------------------
__device__ __forceinline__ float2 f2_add(float2 a, float2 b) {
    float2 c;
    asm("add.rn.f32x2 %0, %1, %2;"
        : "=l"(*reinterpret_cast<unsigned long long*>(&c))
        : "l"(*reinterpret_cast<const unsigned long long*>(&a)),
          "l"(*reinterpret_cast<const unsigned long long*>(&b)));
    return c;
}
__device__ __forceinline__ float2 f2_fma(float2 a, float2 b, float2 c) {
    float2 d;
    asm("fma.rn.f32x2 %0, %1, %2, %3;"
        : "=l"(*reinterpret_cast<unsigned long long*>(&d))
        : "l"(*reinterpret_cast<const unsigned long long*>(&a)),
          "l"(*reinterpret_cast<const unsigned long long*>(&b)),
          "l"(*reinterpret_cast<const unsigned long long*>(&c)));
    return d;
}

// ---------------------------------------------------------------------------
// Kernel A: per-node projections. 256 blocks x 256 threads, 4 nodes/block,
// 2 blocks/SM -> full SM coverage. Padded smem: conflict-free transpose.
// ---------------------------------------------------------------------------
__global__ __launch_bounds__(256, 2) void gat_pre_kernel(
    const float* __restrict__ x,
    const float* __restrict__ f_w,   // [DD][2*DD] row-major
    const float* __restrict__ f_b,   // [DD]
    const float* __restrict__ w_w)   // [1][2*DD]
{
    __shared__ float fw_sh[128 * 65]; // fw_sh[k*65+d] = f_w[d*128 + k]
    __shared__ float xs[4][DD];
    __shared__ float w1_sh[DD];
    __shared__ float sred[4][2];

    const int tid   = threadIdx.x;
    const int node0 = blockIdx.x * 4;

    for (int i = tid; i < DD * 128; i += 256)
        fw_sh[(i & 127) * 65 + (i >> 7)] = f_w[i];   // conflict-free
    if (tid < DD) w1_sh[tid] = w_w[tid];
    if (tid < 4 * DD) xs[tid >> 6][tid & 63] = x[node0 * DD + tid];
    __syncthreads();

    const int ln   = tid >> 6;   // local node 0..3
    const int d    = tid & 63;
    const int node = node0 + ln;

    float a1 = 0.f, a2 = 0.f;
#pragma unroll
    for (int k = 0; k < DD; ++k) {
        float xa = xs[ln][k];
        a1 = fmaf(xa, fw_sh[k * 65 + d], a1);
        a2 = fmaf(xa, fw_sh[(DD + k) * 65 + d], a2);
    }
    g_ssrc[node * DD + d] = a1;
    g_t[node * DD + d]    = a2 + f_b[d];

    float p = xs[ln][d] * w1_sh[d];
#pragma unroll
    for (int off = 16; off > 0; off >>= 1)
        p += __shfl_down_sync(0xffffffffu, p, off);
    if ((tid & 31) == 0) sred[ln][(tid >> 5) & 1] = p;
    __syncthreads();
    if (d == 0) g_s1[node] = sred[ln][0] + sred[ln][1];
}

// ---------------------------------------------------------------------------
// Kernel B: masked softmax + weighted-relu contraction.
// 256 blocks (TI=4 rows) x 512 threads, 2 CTAs/SM.
// Main loop: ONE warp-wide LDG.128 covers TWO s_src rows (lanes 0-15 = row
// 2jj, lanes 16-31 = row 2jj+1); each half-warp computes all 4 output rows
// for its j. 32 iterations, 1 LDG + 2 LDS + 32 arith each.
// ---------------------------------------------------------------------------
__global__ __launch_bounds__(512, 2) void gat_main_kernel(
    const int* __restrict__ adj,
    float* __restrict__ out)
{
    __shared__ float2 att2[NN * TI];   // att2[j*4+r] = {e,e}  (32 KB)
    __shared__ float  s1_sh[NN];       // 4 KB
    __shared__ float  t_sh[TI * DD];   // 1 KB
    __shared__ float  wsum[16 * TI];
    __shared__ float  rowinv[TI];

    const int tid  = threadIdx.x;
    const int row0 = blockIdx.x * TI;
    const int wid  = tid >> 5;
    const int lane = tid & 31;

    for (int i = tid; i < NN; i += 512) s1_sh[i] = g_s1[i];
    if (tid < TI * DD) t_sh[tid] = g_t[row0 * DD + tid];
    __syncthreads();

    // --- softmax numerators: e[j][r] = adj[r][j]>0 ? exp(s1[j]) : 0 ---------
    {
        float ls[TI] = {0.f, 0.f, 0.f, 0.f};
#pragma unroll
        for (int k = 0; k < 2; ++k) {
            int j = wid * 64 + k * 32 + lane;
            float ev = __expf(s1_sh[j]);
#pragma unroll
            for (int rr = 0; rr < TI; ++rr) {
                int a = adj[(row0 + rr) * NN + j];          // coalesced
                float e = (a > 0) ? ev : 0.f;
                att2[j * TI + rr] = make_float2(e, e);
                ls[rr] += e;
            }
        }
#pragma unroll
        for (int rr = 0; rr < TI; ++rr) {
            float v = ls[rr];
#pragma unroll
            for (int off = 16; off > 0; off >>= 1)
                v += __shfl_xor_sync(0xffffffffu, v, off);
            if (lane == 0) wsum[wid * TI + rr] = v;
        }
    }
    __syncthreads();
    if (tid < TI) {
        float s = 0.f;
#pragma unroll
        for (int g = 0; g < 16; ++g) s += wsum[g * TI + tid];
        rowinv[tid] = 1.f / s;
    }

    // --- contraction: acc[r] += e[j][r] * relu(s_src[j] + t[r]) -------------
    const int h = lane >> 4;         // j parity handled by this half-warp
    const int q = lane & 15;         // d quad: d = 4q..4q+3
    const int jg = wid;              // j group: [jg*64, (jg+1)*64)

    float2 t2[TI][2];
#pragma unroll
    for (int rr = 0; rr < TI; ++rr)
#pragma unroll
        for (int p = 0; p < 2; ++p)
            t2[rr][p] = *reinterpret_cast<const float2*>(
                &t_sh[rr * DD + 4 * q + 2 * p]);

    float2 acc[TI][2];
#pragma unroll
    for (int rr = 0; rr < TI; ++rr)
        acc[rr][0] = acc[rr][1] = make_float2(0.f, 0.f);

    // lane address: row (2*jj + h), quad q  -> one 512B warp-wide LDG.128
    const float4* __restrict__ sp4 =
        reinterpret_cast<const float4*>(g_ssrc + (jg * 64 + h) * DD) + q;
    // e for row (2*jj + h): two float4s {e0,e0,e1,e1} / {e2,e2,e3,e3}
    const float4* __restrict__ ap4 =
        reinterpret_cast<const float4*>(att2 + (jg * 64 + h) * TI);

#pragma unroll 8
    for (int jj = 0; jj < 32; ++jj) {
        float4 s4 = sp4[jj * 32];            // rows 2jj & 2jj+1 in one LDG
        float4 eA = ap4[jj * 4];             // {e0,e0,e1,e1} (bcast per half)
        float4 eB = ap4[jj * 4 + 1];         // {e2,e2,e3,e3}
        float2 sa = make_float2(s4.x, s4.y);
        float2 sb = make_float2(s4.z, s4.w);

#define GAT_STEP(RR, EPAIR)                                  \
        {                                                    \
            float2 ua = f2_add(sa, t2[RR][0]);               \
            float2 ub = f2_add(sb, t2[RR][1]);               \
            ua.x = fmaxf(ua.x, 0.f);  ua.y = fmaxf(ua.y, 0.f); \
            ub.x = fmaxf(ub.x, 0.f);  ub.y = fmaxf(ub.y, 0.f); \
            acc[RR][0] = f2_fma((EPAIR), ua, acc[RR][0]);    \
            acc[RR][1] = f2_fma((EPAIR), ub, acc[RR][1]);    \
        }
        GAT_STEP(0, make_float2(eA.x, eA.y))
        GAT_STEP(1, make_float2(eA.z, eA.w))
        GAT_STEP(2, make_float2(eB.x, eB.y))
        GAT_STEP(3, make_float2(eB.z, eB.w))
#undef GAT_STEP
    }

    // --- epilogue: reduce 32 half-warp partials, normalize, store -----------
    __syncthreads();                       // everyone done reading att2
    float* part = reinterpret_cast<float*>(att2);   // reuse: [32][TI][DD]
#pragma unroll
    for (int rr = 0; rr < TI; ++rr) {
        float4 v = make_float4(acc[rr][0].x, acc[rr][0].y,
                               acc[rr][1].x, acc[rr][1].y);
        *reinterpret_cast<float4*>(
            &part[((jg * 2 + h) * TI + rr) * DD + 4 * q]) = v;
    }
    __syncthreads();

    if (tid < TI * DD) {                   // 256 threads: (rr, d)
        int rr = tid >> 6;
        int d  = tid & 63;
        float s = 0.f;
#pragma unroll
        for (int g = 0; g < 32; ++g)
            s += part[(g * TI + rr) * DD + d];
        out[(row0 + rr) * DD + d] = s * rowinv[rr];
    }
}

// ---------------------------------------------------------------------------
// Inputs (metadata order): 0 x[1024,64] f32, 1 adj[1024,1024] i32,
// 2 src i64 (unused), 3 tgt i64 (unused), 4 Msrc (unused), 5 Mtgt (unused),
// 6 f_w[64,128] f32, 7 f_b[64] f32, 8 w_w[1,128] f32, 9 w_b[1] f32 (cancels).
// Output: o[1024,64] f32.
// ---------------------------------------------------------------------------
extern "C" void kernel_launch(void* const* d_in, const int* in_sizes, int n_in,
                              void* d_out, int out_size)
{
    const float* x   = (const float*)d_in[0];
    const int*   adj = (const int*)d_in[1];
    const float* f_w = (const float*)d_in[6];
    const float* f_b = (const float*)d_in[7];
    const float* w_w = (const float*)d_in[8];
    float* out = (float*)d_out;

    gat_pre_kernel<<<256, 256>>>(x, f_w, f_b, w_w);
    gat_main_kernel<<<NN / TI, 512>>>(adj, out);
}